// round 1
// baseline (speedup 1.0000x reference)
#include <cuda_runtime.h>
#include <cuda_bf16.h>

// Problem constants
namespace {
constexpr int Bn = 4, Tn = 2048, Cn = 1024, Hn = 16, Dn = 64;
constexpr int BM = 64, BN = 64, BK = 16;
}

// Scratch (device globals — no allocation allowed)
__device__ __align__(16) float g_q[Bn * Hn * Tn * Dn];   // 32 MB, [B,H,T,D], pre-scaled by D^-0.5
__device__ __align__(16) float g_k[Bn * Hn * Tn * Dn];   // 32 MB
__device__ __align__(16) float g_v[Bn * Hn * Tn * Dn];   // 32 MB
__device__ __align__(16) float g_ao[Bn * Tn * Cn];       // 32 MB, [B,T,C] attention output

// ---------------------------------------------------------------------------
// NT GEMM: C[m,n] = sum_k A[m,k] * Bm[n,k]
// MODE 0: A = x, Bm = w_qkv; scatter into g_q/g_k/g_v ([B,H,T,D]), q scaled.
// MODE 1: A = g_ao, Bm = w_out; C = A*Bm^T + bias -> Cout.
// BM=BN=64, BK=16, 256 threads, 4x4 microtile per thread.
// ---------------------------------------------------------------------------
template <int MODE>
__global__ __launch_bounds__(256) void gemm_nt(
    const float* __restrict__ Ain, const float* __restrict__ Bm,
    const float* __restrict__ bias, float* __restrict__ Cout,
    int M, int N, int K)
{
    const float* A = (MODE == 1) ? (const float*)g_ao : Ain;
    __shared__ float As[BK][BM];
    __shared__ float Bs[BK][BN];

    const int tid = threadIdx.x;          // 0..255
    const int tx = tid & 15;              // n microtile
    const int ty = tid >> 4;              // m microtile
    const int m0 = blockIdx.y * BM;
    const int n0 = blockIdx.x * BN;

    // Global->shared load mapping: each thread loads one float4 of A and B
    const int lr = tid >> 2;              // 0..63 (row within tile)
    const int lc = (tid & 3) << 2;        // 0,4,8,12 (k offset)

    const float* aptr = A  + (size_t)(m0 + lr) * K + lc;
    const float* bptr = Bm + (size_t)(n0 + lr) * K + lc;

    float acc[4][4] = {};

    for (int k0 = 0; k0 < K; k0 += BK) {
        float4 a4 = *(const float4*)(aptr + k0);
        float4 b4 = *(const float4*)(bptr + k0);
        As[lc + 0][lr] = a4.x; As[lc + 1][lr] = a4.y;
        As[lc + 2][lr] = a4.z; As[lc + 3][lr] = a4.w;
        Bs[lc + 0][lr] = b4.x; Bs[lc + 1][lr] = b4.y;
        Bs[lc + 2][lr] = b4.z; Bs[lc + 3][lr] = b4.w;
        __syncthreads();

#pragma unroll
        for (int k = 0; k < BK; k++) {
            float4 ra = *(const float4*)&As[k][ty * 4];
            float4 rb = *(const float4*)&Bs[k][tx * 4];
            float ar[4] = {ra.x, ra.y, ra.z, ra.w};
            float br[4] = {rb.x, rb.y, rb.z, rb.w};
#pragma unroll
            for (int i = 0; i < 4; i++)
#pragma unroll
                for (int j = 0; j < 4; j++)
                    acc[i][j] = fmaf(ar[i], br[j], acc[i][j]);
        }
        __syncthreads();
    }

    if (MODE == 0) {
        // n0 is a multiple of 64 => whole block maps to one (section, head)
        const int sec = n0 / Cn;                 // 0=q, 1=k, 2=v
        const int h = (n0 % Cn) / Dn;
        const float scale = (sec == 0) ? 0.125f : 1.0f;   // D^-0.5 folded into q
        float* dst = (sec == 0) ? g_q : (sec == 1) ? g_k : g_v;
#pragma unroll
        for (int i = 0; i < 4; i++) {
            const int m = m0 + ty * 4 + i;
            const int b = m / Tn, t = m % Tn;
            float* row = dst + (size_t)((b * Hn + h) * Tn + t) * Dn + tx * 4;
#pragma unroll
            for (int j = 0; j < 4; j++) row[j] = acc[i][j] * scale;
        }
    } else {
#pragma unroll
        for (int i = 0; i < 4; i++) {
            const int m = m0 + ty * 4 + i;
            float* row = Cout + (size_t)m * N + n0 + tx * 4;
#pragma unroll
            for (int j = 0; j < 4; j++)
                row[j] = acc[i][j] + bias[n0 + tx * 4 + j];
        }
    }
}

// ---------------------------------------------------------------------------
// Causal flash attention (fp32, online softmax).
// Grid: (Tn/64, Bn*Hn). Block: 64 threads; thread t owns query row
// qi = blockIdx.x*64 + t within head blockIdx.y. K/V tiles of 32 rows in SMEM.
// q already carries the D^-0.5 scale.
// ---------------------------------------------------------------------------
__global__ __launch_bounds__(64) void attn_fwd()
{
    __shared__ float4 Ks[32 * 16];   // 32 keys x 64 dims
    __shared__ float4 Vs[32 * 16];

    const int tid = threadIdx.x;
    const int bh = blockIdx.y;
    const float4* qb = (const float4*)(g_q + (size_t)bh * Tn * Dn);
    const float4* kb = (const float4*)(g_k + (size_t)bh * Tn * Dn);
    const float4* vb = (const float4*)(g_v + (size_t)bh * Tn * Dn);

    const int qi = blockIdx.x * 64 + tid;

    float4 qr[16];
#pragma unroll
    for (int c = 0; c < 16; c++) qr[c] = qb[qi * 16 + c];

    float4 acc[16] = {};
    float mrun = -1e30f, lrun = 0.0f;

    const int nkt = blockIdx.x * 2 + 2;   // key tiles covering [0, blockIdx.x*64+64)

    for (int kt = 0; kt < nkt; kt++) {
        const int k0 = kt * 32;
        __syncthreads();
#pragma unroll 4
        for (int i = tid; i < 512; i += 64) {
            Ks[i] = kb[k0 * 16 + i];
            Vs[i] = vb[k0 * 16 + i];
        }
        __syncthreads();

        float s[32];
#pragma unroll
        for (int r = 0; r < 32; r++) {
            float sum = 0.0f;
#pragma unroll
            for (int c = 0; c < 16; c++) {
                float4 kk = Ks[r * 16 + c];
                sum = fmaf(qr[c].x, kk.x, sum);
                sum = fmaf(qr[c].y, kk.y, sum);
                sum = fmaf(qr[c].z, kk.z, sum);
                sum = fmaf(qr[c].w, kk.w, sum);
            }
            s[r] = (k0 + r <= qi) ? sum : -1e30f;
        }

        float tm = -1e30f;
#pragma unroll
        for (int r = 0; r < 32; r++) tm = fmaxf(tm, s[r]);
        const float newm = fmaxf(mrun, tm);
        const float corr = __expf(mrun - newm);
        lrun *= corr;
#pragma unroll
        for (int c = 0; c < 16; c++) {
            acc[c].x *= corr; acc[c].y *= corr;
            acc[c].z *= corr; acc[c].w *= corr;
        }
#pragma unroll
        for (int r = 0; r < 32; r++) {
            const float p = __expf(s[r] - newm);
            lrun += p;
#pragma unroll
            for (int c = 0; c < 16; c++) {
                float4 vv = Vs[r * 16 + c];
                acc[c].x = fmaf(p, vv.x, acc[c].x);
                acc[c].y = fmaf(p, vv.y, acc[c].y);
                acc[c].z = fmaf(p, vv.z, acc[c].z);
                acc[c].w = fmaf(p, vv.w, acc[c].w);
            }
        }
        mrun = newm;
    }

    const float inv = 1.0f / lrun;
    const int b = bh >> 4, h = bh & 15;
    float4* dst = (float4*)(g_ao + (size_t)(b * Tn + qi) * Cn + h * Dn);
#pragma unroll
    for (int c = 0; c < 16; c++) {
        float4 o;
        o.x = acc[c].x * inv; o.y = acc[c].y * inv;
        o.z = acc[c].z * inv; o.w = acc[c].w * inv;
        dst[c] = o;
    }
}

// ---------------------------------------------------------------------------
// Launch: inputs per metadata order: x, w_qkv, w_out, b_out. Output fp32.
// ---------------------------------------------------------------------------
extern "C" void kernel_launch(void* const* d_in, const int* in_sizes, int n_in,
                              void* d_out, int out_size)
{
    const float* x     = (const float*)d_in[0];  // [4,2048,1024]
    const float* w_qkv = (const float*)d_in[1];  // [3072,1024]
    const float* w_out = (const float*)d_in[2];  // [1024,1024]
    const float* b_out = (const float*)d_in[3];  // [1024]
    float* out = (float*)d_out;                  // [4,2048,1024]

    const int M = Bn * Tn;        // 8192

    // 1) QKV projection -> scatter to g_q/g_k/g_v
    gemm_nt<0><<<dim3((3 * Cn) / BN, M / BM), 256>>>(x, w_qkv, nullptr, nullptr,
                                                     M, 3 * Cn, Cn);
    // 2) Causal attention -> g_ao
    attn_fwd<<<dim3(Tn / 64, Bn * Hn), 64>>>();
    // 3) Output projection + bias -> d_out
    gemm_nt<1><<<dim3(Cn / BN, M / BM), 256>>>(nullptr, w_out, b_out, out,
                                               M, Cn, Cn);
}